// round 7
// baseline (speedup 1.0000x reference)
#include <cuda_runtime.h>
#include <cuda_bf16.h>

#define BATCH 1024
#define SEQ   512
#define HID   64
#define GATES 256
#define NR    8
#define NCTA  (BATCH / NR)   // 128
#define NTHR  256            // 8 warps = 4 groups x 2 cell-half warps

typedef unsigned long long ull;

struct __align__(16) Smem {
    // Weight layout: W[k][col], col = j*4 + hq (cell j, gate hq: 0=i,1=f,2=g,3=o)
    float W1[HID][GATES];          //  64 KB (W_hh1)
    float W2[2 * HID][GATES];      // 128 KB ([W_ih2 ; W_hh2])
    float hb[2 * HID][NR];         //   4 KB [k][row]; k<64: h1, k>=64: h2
    ulonglong2 pexA[4][2][64];     //   8 KB [group][slot][cell] gates (i,f)
    ulonglong2 pexB[4][2][64];     //   8 KB gates (g,o)
    float wih1v[GATES];
    float b1v[GATES];
    float b2v[GATES];
    float wlin[HID];
    float xs[2][NR];
    float outp[2][2][4];           // [row-quad][hh][row-in-quad]
    float blin;
};   // ~216.6 KB

__device__ __forceinline__ ull pk2(float lo, float hi) {
    ull r; asm("mov.b64 %0, {%1, %2};" : "=l"(r) : "f"(lo), "f"(hi)); return r;
}
__device__ __forceinline__ void unpk(ull v, float& lo, float& hi) {
    asm("mov.b64 {%0, %1}, %2;" : "=f"(lo), "=f"(hi) : "l"(v));
}
__device__ __forceinline__ void fma2(ull& d, ull a, ull b) {
    asm("fma.rn.f32x2 %0, %1, %2, %0;" : "+l"(d) : "l"(a), "l"(b));
}
__device__ __forceinline__ ull add2(ull a, ull b) {
    ull d; asm("add.rn.f32x2 %0, %1, %2;" : "=l"(d) : "l"(a), "l"(b)); return d;
}

__device__ __forceinline__ float sigf(float v) {
    float e = __expf(-v);
    return __fdividef(1.0f, 1.0f + e);
}
__device__ __forceinline__ float tanhf_(float v) {
    float e = __expf(2.0f * v);
    return 1.0f - __fdividef(2.0f, 1.0f + e);
}

// 8 k-steps: acc[q][p] += h[k][rows 2p,2p+1] * w[k][cell*4+q]
__device__ __forceinline__ void gemm8(const float* __restrict__ wp,
                                      const float* __restrict__ hp,
                                      ull acc[4][4]) {
#pragma unroll
    for (int kk = 0; kk < 8; kk++) {
        float4 wv = *reinterpret_cast<const float4*>(wp + kk * GATES);
        ulonglong2 hA = *reinterpret_cast<const ulonglong2*>(hp + kk * 8);
        ulonglong2 hB = *reinterpret_cast<const ulonglong2*>(hp + kk * 8 + 4);
        ull w;
        w = pk2(wv.x, wv.x);
        fma2(acc[0][0], hA.x, w); fma2(acc[0][1], hA.y, w);
        fma2(acc[0][2], hB.x, w); fma2(acc[0][3], hB.y, w);
        w = pk2(wv.y, wv.y);
        fma2(acc[1][0], hA.x, w); fma2(acc[1][1], hA.y, w);
        fma2(acc[1][2], hB.x, w); fma2(acc[1][3], hB.y, w);
        w = pk2(wv.z, wv.z);
        fma2(acc[2][0], hA.x, w); fma2(acc[2][1], hA.y, w);
        fma2(acc[2][2], hB.x, w); fma2(acc[2][3], hB.y, w);
        w = pk2(wv.w, wv.w);
        fma2(acc[3][0], hA.x, w); fma2(acc[3][1], hA.y, w);
        fma2(acc[3][2], hB.x, w); fma2(acc[3][3], hB.y, w);
    }
}

// LSTM cell for a packed row-pair: gates (i,f,g,o) each f32x2 -> h f32x2.
__device__ __forceinline__ ull act2(ull ai, ull af, ull ag, ull ao,
                                    float& ca, float& cb) {
    float i0, i1, f0, f1, g0, g1, o0, o1;
    unpk(ai, i0, i1); unpk(af, f0, f1);
    unpk(ag, g0, g1); unpk(ao, o0, o1);
    float cA = sigf(f0) * ca + sigf(i0) * tanhf_(g0);
    float cB = sigf(f1) * cb + sigf(i1) * tanhf_(g1);
    ca = cA; cb = cB;
    return pk2(sigf(o0) * tanhf_(cA), sigf(o1) * tanhf_(cB));
}

__global__ void __launch_bounds__(NTHR, 1)
lstm_persistent_kernel(const float* __restrict__ x,
                       const float* __restrict__ Wih1, const float* __restrict__ Whh1,
                       const float* __restrict__ bih1, const float* __restrict__ bhh1,
                       const float* __restrict__ Wih2, const float* __restrict__ Whh2,
                       const float* __restrict__ bih2, const float* __restrict__ bhh2,
                       const float* __restrict__ Wlin, const float* __restrict__ blin,
                       float* __restrict__ out) {
    extern __shared__ char smem_raw[];
    Smem& sm = *reinterpret_cast<Smem*>(smem_raw);

    const int tid  = threadIdx.x;
    const int wid  = tid >> 5;
    const int lane = tid & 31;
    const int row0 = blockIdx.x * NR;

    // ---- one-time staging ----
    for (int i = tid; i < GATES * HID; i += NTHR) {
        int gsrc = i >> 6, k = i & 63;
        int col = (gsrc & 63) * 4 + (gsrc >> 6);
        sm.W1[k][col]      = Whh1[i];
        sm.W2[k][col]      = Wih2[i];
        sm.W2[64 + k][col] = Whh2[i];
    }
    for (int gsrc = tid; gsrc < GATES; gsrc += NTHR) {
        int col = (gsrc & 63) * 4 + (gsrc >> 6);
        sm.wih1v[col] = Wih1[gsrc];
        sm.b1v[col]   = bih1[gsrc] + bhh1[gsrc];
        sm.b2v[col]   = bih2[gsrc] + bhh2[gsrc];
    }
    if (tid < HID) sm.wlin[tid] = Wlin[tid];
    if (tid == 0)  sm.blin = blin[0];
    for (int i = tid; i < 2 * HID * NR; i += NTHR)
        reinterpret_cast<float*>(sm.hb)[i] = 0.0f;
    if (tid < NR) {
        sm.xs[1][tid] = x[(row0 + tid) * SEQ + 0];  // x(0) for prologue
        sm.xs[0][tid] = x[(row0 + tid) * SEQ + 1];  // x(1) for GEMM(0)
    }
    __syncthreads();

    const int g    = wid >> 1;          // group: 0,1 -> gates2; 2,3 -> gates1(next)
    const int hh   = wid & 1;           // cell half
    const int j    = hh * 32 + lane;    // owned cell
    const int c4   = j * 4;
    const int own0 = (g & 1) * 2;       // first owned row-pair (0 or 2)
    const int rb   = own0 * 2;          // first owned row

    float cs[4] = {0.f, 0.f, 0.f, 0.f}; // c-state: rows rb..rb+3 of cell j
                                        // (g<2: layer2 cell state; g>=2: layer1)
    const float wl = sm.wlin[j];

    // ---- prologue: gates1(0) = b1 + x(0)*wih1  (h1(-1)=0), groups 2,3 only ----
    if (g >= 2) {
        float4 wiv = *reinterpret_cast<const float4*>(&sm.wih1v[c4]);
        float4 bv  = *reinterpret_cast<const float4*>(&sm.b1v[c4]);
        ulonglong2 xq = *reinterpret_cast<const ulonglong2*>(&sm.xs[1][rb]);
        ull b, w;
        ull gi0, gf0, gg0, go0, gi1, gf1, gg1, go1;
        b = pk2(bv.x, bv.x); w = pk2(wiv.x, wiv.x);
        gi0 = b; fma2(gi0, xq.x, w); gi1 = b; fma2(gi1, xq.y, w);
        b = pk2(bv.y, bv.y); w = pk2(wiv.y, wiv.y);
        gf0 = b; fma2(gf0, xq.x, w); gf1 = b; fma2(gf1, xq.y, w);
        b = pk2(bv.z, bv.z); w = pk2(wiv.z, wiv.z);
        gg0 = b; fma2(gg0, xq.x, w); gg1 = b; fma2(gg1, xq.y, w);
        b = pk2(bv.w, bv.w); w = pk2(wiv.w, wiv.w);
        go0 = b; fma2(go0, xq.x, w); go1 = b; fma2(go1, xq.y, w);
        ull h0p = act2(gi0, gf0, gg0, go0, cs[0], cs[1]);
        ull h1p = act2(gi1, gf1, gg1, go1, cs[2], cs[3]);
        *reinterpret_cast<ull*>(&sm.hb[j][rb])     = h0p;
        *reinterpret_cast<ull*>(&sm.hb[j][rb + 2]) = h1p;
    }
    __syncthreads();

    for (int t = 0; t < SEQ; t++) {
        // finalize out[t-1]
        if (t > 0 && tid < NR) {
            out[(row0 + tid) * SEQ + (t - 1)] =
                sm.blin + sm.outp[tid >> 2][0][tid & 3] + sm.outp[tid >> 2][1][tid & 3];
        }

        // ===== fused GEMM phase: gates2(t) [groups 0,1] + gates1(t+1) [groups 2,3]
        ull acc[4][4];
        if (g < 2) {
            if (g == 0) {
                float4 bv = *reinterpret_cast<const float4*>(&sm.b2v[c4]);
                ull b;
                b = pk2(bv.x, bv.x); acc[0][0]=b; acc[0][1]=b; acc[0][2]=b; acc[0][3]=b;
                b = pk2(bv.y, bv.y); acc[1][0]=b; acc[1][1]=b; acc[1][2]=b; acc[1][3]=b;
                b = pk2(bv.z, bv.z); acc[2][0]=b; acc[2][1]=b; acc[2][2]=b; acc[2][3]=b;
                b = pk2(bv.w, bv.w); acc[3][0]=b; acc[3][1]=b; acc[3][2]=b; acc[3][3]=b;
            } else {
#pragma unroll
                for (int q = 0; q < 4; q++)
#pragma unroll
                    for (int p = 0; p < 4; p++) acc[q][p] = 0ull;
            }
            // k-range [g*64, g*64+64): g0 = W_ih2 * h1(t), g1 = W_hh2 * h2(t-1)
            const float* wp = &sm.W2[g * 64][c4];
            const float* hp = &sm.hb[g * 64][0];
#pragma unroll 1
            for (int kb = 0; kb < 8; kb++) {
                gemm8(wp, hp, acc);
                wp += 8 * GATES; hp += 8 * NR;
            }
        } else {
            if (g == 2) {
                float4 wiv = *reinterpret_cast<const float4*>(&sm.wih1v[c4]);
                float4 bv  = *reinterpret_cast<const float4*>(&sm.b1v[c4]);
                const float* xp = sm.xs[t & 1];   // x(t+1)
                ulonglong2 xA = *reinterpret_cast<const ulonglong2*>(xp);
                ulonglong2 xB = *reinterpret_cast<const ulonglong2*>(xp + 4);
                ull b, w;
                b = pk2(bv.x, bv.x); acc[0][0]=b; acc[0][1]=b; acc[0][2]=b; acc[0][3]=b;
                b = pk2(bv.y, bv.y); acc[1][0]=b; acc[1][1]=b; acc[1][2]=b; acc[1][3]=b;
                b = pk2(bv.z, bv.z); acc[2][0]=b; acc[2][1]=b; acc[2][2]=b; acc[2][3]=b;
                b = pk2(bv.w, bv.w); acc[3][0]=b; acc[3][1]=b; acc[3][2]=b; acc[3][3]=b;
                w = pk2(wiv.x, wiv.x);
                fma2(acc[0][0], xA.x, w); fma2(acc[0][1], xA.y, w);
                fma2(acc[0][2], xB.x, w); fma2(acc[0][3], xB.y, w);
                w = pk2(wiv.y, wiv.y);
                fma2(acc[1][0], xA.x, w); fma2(acc[1][1], xA.y, w);
                fma2(acc[1][2], xB.x, w); fma2(acc[1][3], xB.y, w);
                w = pk2(wiv.z, wiv.z);
                fma2(acc[2][0], xA.x, w); fma2(acc[2][1], xA.y, w);
                fma2(acc[2][2], xB.x, w); fma2(acc[2][3], xB.y, w);
                w = pk2(wiv.w, wiv.w);
                fma2(acc[3][0], xA.x, w); fma2(acc[3][1], xA.y, w);
                fma2(acc[3][2], xB.x, w); fma2(acc[3][3], xB.y, w);
            } else {
#pragma unroll
                for (int q = 0; q < 4; q++)
#pragma unroll
                    for (int p = 0; p < 4; p++) acc[q][p] = 0ull;
            }
            // k-range [(g-2)*32, ...+32) of W_hh1 * h1(t)
            const float* wp = &sm.W1[(g - 2) * 32][c4];
            const float* hp = &sm.hb[(g - 2) * 32][0];
#pragma unroll 1
            for (int kb = 0; kb < 4; kb++) {
                gemm8(wp, hp, acc);
                wp += 8 * GATES; hp += 8 * NR;
            }
        }

        // ship the row-pairs our k-split partner owns
        {
            int pg = g ^ 1;
            if ((g & 1) == 0) {   // ship rp 2,3
                sm.pexA[pg][0][j] = make_ulonglong2(acc[0][2], acc[1][2]);
                sm.pexA[pg][1][j] = make_ulonglong2(acc[0][3], acc[1][3]);
                sm.pexB[pg][0][j] = make_ulonglong2(acc[2][2], acc[3][2]);
                sm.pexB[pg][1][j] = make_ulonglong2(acc[2][3], acc[3][3]);
            } else {              // ship rp 0,1
                sm.pexA[pg][0][j] = make_ulonglong2(acc[0][0], acc[1][0]);
                sm.pexA[pg][1][j] = make_ulonglong2(acc[0][1], acc[1][1]);
                sm.pexB[pg][0][j] = make_ulonglong2(acc[2][0], acc[3][0]);
                sm.pexB[pg][1][j] = make_ulonglong2(acc[2][1], acc[3][1]);
            }
        }
        __syncthreads();

        // ===== fused reduce + activation: act2(t) [groups 0,1] + act1(t+1) [2,3]
        {
            ulonglong2 rA0 = sm.pexA[g][0][j], rB0 = sm.pexB[g][0][j];
            ulonglong2 rA1 = sm.pexA[g][1][j], rB1 = sm.pexB[g][1][j];
            ull h0p, h1p;
            if ((g & 1) == 0) {   // own rp 0,1
                h0p = act2(add2(acc[0][0], rA0.x), add2(acc[1][0], rA0.y),
                           add2(acc[2][0], rB0.x), add2(acc[3][0], rB0.y),
                           cs[0], cs[1]);
                h1p = act2(add2(acc[0][1], rA1.x), add2(acc[1][1], rA1.y),
                           add2(acc[2][1], rB1.x), add2(acc[3][1], rB1.y),
                           cs[2], cs[3]);
            } else {              // own rp 2,3
                h0p = act2(add2(acc[0][2], rA0.x), add2(acc[1][2], rA0.y),
                           add2(acc[2][2], rB0.x), add2(acc[3][2], rB0.y),
                           cs[0], cs[1]);
                h1p = act2(add2(acc[0][3], rA1.x), add2(acc[1][3], rA1.y),
                           add2(acc[2][3], rB1.x), add2(acc[3][3], rB1.y),
                           cs[2], cs[3]);
            }
            const int hbase = (g < 2) ? 64 : 0;   // h2(t) or h1(t+1)
            *reinterpret_cast<ull*>(&sm.hb[hbase + j][rb])     = h0p;
            *reinterpret_cast<ull*>(&sm.hb[hbase + j][rb + 2]) = h1p;

            if (g < 2) {
                // out(t) partials from h2(t): rows rb..rb+3
                float h0, h1, h2v, h3;
                unpk(h0p, h0, h1); unpk(h1p, h2v, h3);
                float p0 = wl * h0, p1 = wl * h1, p2 = wl * h2v, p3 = wl * h3;
#pragma unroll
                for (int off = 16; off > 0; off >>= 1) {
                    p0 += __shfl_xor_sync(0xffffffffu, p0, off);
                    p1 += __shfl_xor_sync(0xffffffffu, p1, off);
                    p2 += __shfl_xor_sync(0xffffffffu, p2, off);
                    p3 += __shfl_xor_sync(0xffffffffu, p3, off);
                }
                if (lane == 0) {
                    sm.outp[g][hh][0] = p0; sm.outp[g][hh][1] = p1;
                    sm.outp[g][hh][2] = p2; sm.outp[g][hh][3] = p3;
                }
            }
        }
        // prefetch x(t+2) for GEMM(t+1)
        if (tid < NR && (t + 2) < SEQ)
            sm.xs[(t + 1) & 1][tid] = x[(row0 + tid) * SEQ + t + 2];
        __syncthreads();
    }

    if (tid < NR) {
        out[(row0 + tid) * SEQ + (SEQ - 1)] =
            sm.blin + sm.outp[tid >> 2][0][tid & 3] + sm.outp[tid >> 2][1][tid & 3];
    }
}

extern "C" void kernel_launch(void* const* d_in, const int* in_sizes, int n_in,
                              void* d_out, int out_size) {
    const float* x     = (const float*)d_in[0];
    const float* Wih1  = (const float*)d_in[1];
    const float* Whh1  = (const float*)d_in[2];
    const float* bih1  = (const float*)d_in[3];
    const float* bhh1  = (const float*)d_in[4];
    const float* Wih2  = (const float*)d_in[5];
    const float* Whh2  = (const float*)d_in[6];
    const float* bih2  = (const float*)d_in[7];
    const float* bhh2  = (const float*)d_in[8];
    const float* Wlin  = (const float*)d_in[9];
    const float* blin  = (const float*)d_in[10];
    float* out = (float*)d_out;

    (void)in_sizes; (void)n_in; (void)out_size;

    static_assert(sizeof(Smem) <= 232448, "smem over sm_103a opt-in limit");
    cudaFuncSetAttribute(lstm_persistent_kernel,
                         cudaFuncAttributeMaxDynamicSharedMemorySize,
                         (int)sizeof(Smem));
    lstm_persistent_kernel<<<NCTA, NTHR, sizeof(Smem)>>>(
        x, Wih1, Whh1, bih1, bhh1, Wih2, Whh2, bih2, bhh2, Wlin, blin, out);
}

// round 8
// speedup vs baseline: 1.0212x; 1.0212x over previous
#include <cuda_runtime.h>
#include <cuda_bf16.h>

#define BATCH 1024
#define SEQ   512
#define HID   64
#define GATES 256
#define NR    8
#define NCTA  (BATCH / NR)   // 128
#define NTHR  384            // 12 warps: 8 L2-warps (4 k-groups x 2 halves) + 4 L1-warps

typedef unsigned long long ull;

struct __align__(16) Smem {
    // Weight layout: W[k][col], col = j*4 + hq (cell j, gate hq: 0=i,1=f,2=g,3=o)
    float W1[HID][GATES];          //  64 KB (W_hh1)
    float W2[2 * HID][GATES];      // 128 KB ([W_ih2 ; W_hh2])
    float hb[2 * HID][NR];         //   4 KB [k][row]; k<64: h1, k>=64: h2
    ulonglong2 pexA[4][3][64];     //  12 KB [pair][slot][cell] gates (i,f) — L2 only
    ulonglong2 pexB[4][3][64];     //  12 KB gates (g,o)
    float wih1v[GATES];
    float b1v[GATES];
    float b2v[GATES];
    float wlin[HID];
    float xs[2][NR];
    float outp[4][2][2];           // [pair][hh][row-in-pair]
    float blin;
};   // ~223.5 KB

__device__ __forceinline__ ull pk2(float lo, float hi) {
    ull r; asm("mov.b64 %0, {%1, %2};" : "=l"(r) : "f"(lo), "f"(hi)); return r;
}
__device__ __forceinline__ void unpk(ull v, float& lo, float& hi) {
    asm("mov.b64 {%0, %1}, %2;" : "=f"(lo), "=f"(hi) : "l"(v));
}
__device__ __forceinline__ void fma2(ull& d, ull a, ull b) {
    asm("fma.rn.f32x2 %0, %1, %2, %0;" : "+l"(d) : "l"(a), "l"(b));
}
__device__ __forceinline__ ull add2(ull a, ull b) {
    ull d; asm("add.rn.f32x2 %0, %1, %2;" : "=l"(d) : "l"(a), "l"(b)); return d;
}

__device__ __forceinline__ float sigf(float v) {
    float e = __expf(-v);
    return __fdividef(1.0f, 1.0f + e);
}
__device__ __forceinline__ float tanhf_(float v) {
    float e = __expf(2.0f * v);
    return 1.0f - __fdividef(2.0f, 1.0f + e);
}

// 8 k-steps: acc[q][p] += h[k][rows 2p,2p+1] * w[k][cell*4+q]
__device__ __forceinline__ void gemm8(const float* __restrict__ wp,
                                      const float* __restrict__ hp,
                                      ull acc[4][4]) {
#pragma unroll
    for (int kk = 0; kk < 8; kk++) {
        float4 wv = *reinterpret_cast<const float4*>(wp + kk * GATES);
        ulonglong2 hA = *reinterpret_cast<const ulonglong2*>(hp + kk * 8);
        ulonglong2 hB = *reinterpret_cast<const ulonglong2*>(hp + kk * 8 + 4);
        ull w;
        w = pk2(wv.x, wv.x);
        fma2(acc[0][0], hA.x, w); fma2(acc[0][1], hA.y, w);
        fma2(acc[0][2], hB.x, w); fma2(acc[0][3], hB.y, w);
        w = pk2(wv.y, wv.y);
        fma2(acc[1][0], hA.x, w); fma2(acc[1][1], hA.y, w);
        fma2(acc[1][2], hB.x, w); fma2(acc[1][3], hB.y, w);
        w = pk2(wv.z, wv.z);
        fma2(acc[2][0], hA.x, w); fma2(acc[2][1], hA.y, w);
        fma2(acc[2][2], hB.x, w); fma2(acc[2][3], hB.y, w);
        w = pk2(wv.w, wv.w);
        fma2(acc[3][0], hA.x, w); fma2(acc[3][1], hA.y, w);
        fma2(acc[3][2], hB.x, w); fma2(acc[3][3], hB.y, w);
    }
}

// LSTM cell for a packed row-pair: gates (i,f,g,o) each f32x2 -> h f32x2.
__device__ __forceinline__ ull act2(ull ai, ull af, ull ag, ull ao,
                                    float& ca, float& cb) {
    float i0, i1, f0, f1, g0, g1, o0, o1;
    unpk(ai, i0, i1); unpk(af, f0, f1);
    unpk(ag, g0, g1); unpk(ao, o0, o1);
    float cA = sigf(f0) * ca + sigf(i0) * tanhf_(g0);
    float cB = sigf(f1) * cb + sigf(i1) * tanhf_(g1);
    ca = cA; cb = cB;
    return pk2(sigf(o0) * tanhf_(cA), sigf(o1) * tanhf_(cB));
}

// Extract this group's row-pair with static indices (avoid local-mem demotion).
__device__ __forceinline__ void own_pair(const ull acc[4][4], int g,
                                         ull& ai, ull& af, ull& ag, ull& ao) {
    ai = 0; af = 0; ag = 0; ao = 0;
#pragma unroll
    for (int p = 0; p < 4; p++)
        if (p == g) { ai = acc[0][p]; af = acc[1][p]; ag = acc[2][p]; ao = acc[3][p]; }
}

__global__ void __launch_bounds__(NTHR, 1)
lstm_persistent_kernel(const float* __restrict__ x,
                       const float* __restrict__ Wih1, const float* __restrict__ Whh1,
                       const float* __restrict__ bih1, const float* __restrict__ bhh1,
                       const float* __restrict__ Wih2, const float* __restrict__ Whh2,
                       const float* __restrict__ bih2, const float* __restrict__ bhh2,
                       const float* __restrict__ Wlin, const float* __restrict__ blin,
                       float* __restrict__ out) {
    extern __shared__ char smem_raw[];
    Smem& sm = *reinterpret_cast<Smem*>(smem_raw);

    const int tid  = threadIdx.x;
    const int wid  = tid >> 5;
    const int lane = tid & 31;
    const int row0 = blockIdx.x * NR;

    // ---- one-time staging ----
    for (int i = tid; i < GATES * HID; i += NTHR) {
        int gsrc = i >> 6, k = i & 63;
        int col = (gsrc & 63) * 4 + (gsrc >> 6);
        sm.W1[k][col]      = Whh1[i];
        sm.W2[k][col]      = Wih2[i];
        sm.W2[64 + k][col] = Whh2[i];
    }
    for (int gsrc = tid; gsrc < GATES; gsrc += NTHR) {
        int col = (gsrc & 63) * 4 + (gsrc >> 6);
        sm.wih1v[col] = Wih1[gsrc];
        sm.b1v[col]   = bih1[gsrc] + bhh1[gsrc];
        sm.b2v[col]   = bih2[gsrc] + bhh2[gsrc];
    }
    if (tid < HID) sm.wlin[tid] = Wlin[tid];
    if (tid == 0)  sm.blin = blin[0];
    for (int i = tid; i < 2 * HID * NR; i += NTHR)
        reinterpret_cast<float*>(sm.hb)[i] = 0.0f;
    if (tid < NR) {
        sm.xs[1][tid] = x[(row0 + tid) * SEQ + 0];  // x(0) for prologue
        sm.xs[0][tid] = x[(row0 + tid) * SEQ + 1];  // x(1) for GEMM(0)
    }
    __syncthreads();

    const bool isL1 = (wid >= 8);
    const int g    = wid >> 1;                       // L2 group 0..3
    const int hh   = wid & 1;
    const int kh   = lane >> 4;                      // L1 k-half
    const int j    = isL1 ? ((wid - 8) * 16 + (lane & 15)) : (hh * 32 + lane);
    const int c4   = j * 4;

    // c-state: L2 threads hold c2 for pair g (2 cells); L1 threads hold c1 for
    // pairs (2kh, 2kh+1) (4 cells).
    float cs[4] = {0.f, 0.f, 0.f, 0.f};
    const float wl = sm.wlin[j];

    // ---- prologue: gates1(0) = b1 + x(0)*wih1  (h1(-1)=0), L1 warps ----
    if (isL1) {
        float4 wiv = *reinterpret_cast<const float4*>(&sm.wih1v[c4]);
        float4 bv  = *reinterpret_cast<const float4*>(&sm.b1v[c4]);
        ulonglong2 xq = *reinterpret_cast<const ulonglong2*>(&sm.xs[1][4 * kh]);
        ull gp0[4], gp1[4];
        float wivf[4] = {wiv.x, wiv.y, wiv.z, wiv.w};
        float bvf[4]  = {bv.x, bv.y, bv.z, bv.w};
#pragma unroll
        for (int q = 0; q < 4; q++) {
            ull b = pk2(bvf[q], bvf[q]);
            ull w = pk2(wivf[q], wivf[q]);
            gp0[q] = b; fma2(gp0[q], xq.x, w);
            gp1[q] = b; fma2(gp1[q], xq.y, w);
        }
        ull h0p = act2(gp0[0], gp0[1], gp0[2], gp0[3], cs[0], cs[1]);
        ull h1p = act2(gp1[0], gp1[1], gp1[2], gp1[3], cs[2], cs[3]);
        *reinterpret_cast<ulonglong2*>(&sm.hb[j][4 * kh]) = make_ulonglong2(h0p, h1p);
    }
    __syncthreads();

    for (int t = 0; t < SEQ; t++) {
        // finalize out[t-1]
        if (t > 0 && tid < NR) {
            out[(row0 + tid) * SEQ + (t - 1)] =
                sm.blin + sm.outp[tid >> 1][0][tid & 1] + sm.outp[tid >> 1][1][tid & 1];
        }

        // ===== GEMM phase (all 6 groups balanced at 512 FFMA2) =====
        ull acc[4][4];
        {
            // bias/x init
            if (!isL1 && g == 0) {
                float4 bv = *reinterpret_cast<const float4*>(&sm.b2v[c4]);
                ull b;
                b = pk2(bv.x, bv.x); acc[0][0]=b; acc[0][1]=b; acc[0][2]=b; acc[0][3]=b;
                b = pk2(bv.y, bv.y); acc[1][0]=b; acc[1][1]=b; acc[1][2]=b; acc[1][3]=b;
                b = pk2(bv.z, bv.z); acc[2][0]=b; acc[2][1]=b; acc[2][2]=b; acc[2][3]=b;
                b = pk2(bv.w, bv.w); acc[3][0]=b; acc[3][1]=b; acc[3][2]=b; acc[3][3]=b;
            } else if (isL1 && kh == 0) {
                float4 wiv = *reinterpret_cast<const float4*>(&sm.wih1v[c4]);
                float4 bv  = *reinterpret_cast<const float4*>(&sm.b1v[c4]);
                const float* xp = sm.xs[t & 1];   // x(t+1)
                ulonglong2 xA = *reinterpret_cast<const ulonglong2*>(xp);
                ulonglong2 xB = *reinterpret_cast<const ulonglong2*>(xp + 4);
                float wivf[4] = {wiv.x, wiv.y, wiv.z, wiv.w};
                float bvf[4]  = {bv.x, bv.y, bv.z, bv.w};
#pragma unroll
                for (int q = 0; q < 4; q++) {
                    ull b = pk2(bvf[q], bvf[q]);
                    ull w = pk2(wivf[q], wivf[q]);
                    acc[q][0] = b; fma2(acc[q][0], xA.x, w);
                    acc[q][1] = b; fma2(acc[q][1], xA.y, w);
                    acc[q][2] = b; fma2(acc[q][2], xB.x, w);
                    acc[q][3] = b; fma2(acc[q][3], xB.y, w);
                }
            } else {
#pragma unroll
                for (int q = 0; q < 4; q++)
#pragma unroll
                    for (int p = 0; p < 4; p++) acc[q][p] = 0ull;
            }
            // uniform 32-k GEMM (4 x gemm8)
            const float* wp;
            const float* hp;
            if (!isL1) {   // gates2(t): k in [g*32, g*32+32) of W2 over [h1;h2]
                wp = &sm.W2[g * 32][c4];
                hp = &sm.hb[g * 32][0];
            } else {       // gates1(t+1): k in [kh*32, kh*32+32) of W1 over h1(t)
                wp = &sm.W1[kh * 32][c4];
                hp = &sm.hb[kh * 32][0];
            }
#pragma unroll 1
            for (int kb = 0; kb < 4; kb++) {
                gemm8(wp, hp, acc);
                wp += 8 * GATES; hp += 8 * NR;
            }
        }

        // ship L2 partials (L1 exchanges via shuffle, no SMEM)
        if (!isL1) {
#pragma unroll
            for (int p = 0; p < 4; p++)
                if (p != g) {
                    int s = (g < p) ? g : g - 1;
                    sm.pexA[p][s][j] = make_ulonglong2(acc[0][p], acc[1][p]);
                    sm.pexB[p][s][j] = make_ulonglong2(acc[2][p], acc[3][p]);
                }
        }
        __syncthreads();

        // ===== ACT phase =====
        if (!isL1) {
            // reduce 4-way over SMEM, activate pair g -> h2(t)
            ull ai, af, ag, ao;
            own_pair(acc, g, ai, af, ag, ao);
#pragma unroll
            for (int s = 0; s < 3; s++) {
                ulonglong2 ra = sm.pexA[g][s][j];
                ulonglong2 rb = sm.pexB[g][s][j];
                ai = add2(ai, ra.x); af = add2(af, ra.y);
                ag = add2(ag, rb.x); ao = add2(ao, rb.y);
            }
            ull h2p = act2(ai, af, ag, ao, cs[0], cs[1]);
            *reinterpret_cast<ull*>(&sm.hb[64 + j][2 * g]) = h2p;

            // out(t) partials: rows 2g, 2g+1, reduced over this warp's 32 cells
            float h0, h1;
            unpk(h2p, h0, h1);
            float p0 = wl * h0, p1 = wl * h1;
#pragma unroll
            for (int off = 16; off > 0; off >>= 1) {
                p0 += __shfl_xor_sync(0xffffffffu, p0, off);
                p1 += __shfl_xor_sync(0xffffffffu, p1, off);
            }
            if (lane == 0) {
                sm.outp[g][hh][0] = p0;
                sm.outp[g][hh][1] = p1;
            }
        } else {
            // intra-warp 2-way k-reduce via xor-16 shuffle, activate pairs (2kh, 2kh+1)
            ull gp0[4], gp1[4];
#pragma unroll
            for (int q = 0; q < 4; q++) {
                ull s0 = kh ? acc[q][0] : acc[q][2];
                ull s1 = kh ? acc[q][1] : acc[q][3];
                ull r0 = __shfl_xor_sync(0xffffffffu, s0, 16);
                ull r1 = __shfl_xor_sync(0xffffffffu, s1, 16);
                ull o0 = kh ? acc[q][2] : acc[q][0];
                ull o1 = kh ? acc[q][3] : acc[q][1];
                gp0[q] = add2(o0, r0);
                gp1[q] = add2(o1, r1);
            }
            ull h0p = act2(gp0[0], gp0[1], gp0[2], gp0[3], cs[0], cs[1]);
            ull h1p = act2(gp1[0], gp1[1], gp1[2], gp1[3], cs[2], cs[3]);
            *reinterpret_cast<ulonglong2*>(&sm.hb[j][4 * kh]) = make_ulonglong2(h0p, h1p);
        }
        // prefetch x(t+2)
        if (tid < NR && (t + 2) < SEQ)
            sm.xs[(t + 1) & 1][tid] = x[(row0 + tid) * SEQ + t + 2];
        __syncthreads();
    }

    if (tid < NR) {
        out[(row0 + tid) * SEQ + (SEQ - 1)] =
            sm.blin + sm.outp[tid >> 1][0][tid & 1] + sm.outp[tid >> 1][1][tid & 1];
    }
}

extern "C" void kernel_launch(void* const* d_in, const int* in_sizes, int n_in,
                              void* d_out, int out_size) {
    const float* x     = (const float*)d_in[0];
    const float* Wih1  = (const float*)d_in[1];
    const float* Whh1  = (const float*)d_in[2];
    const float* bih1  = (const float*)d_in[3];
    const float* bhh1  = (const float*)d_in[4];
    const float* Wih2  = (const float*)d_in[5];
    const float* Whh2  = (const float*)d_in[6];
    const float* bih2  = (const float*)d_in[7];
    const float* bhh2  = (const float*)d_in[8];
    const float* Wlin  = (const float*)d_in[9];
    const float* blin  = (const float*)d_in[10];
    float* out = (float*)d_out;

    (void)in_sizes; (void)n_in; (void)out_size;

    static_assert(sizeof(Smem) <= 232448, "smem over sm_103a opt-in limit");
    cudaFuncSetAttribute(lstm_persistent_kernel,
                         cudaFuncAttributeMaxDynamicSharedMemorySize,
                         (int)sizeof(Smem));
    lstm_persistent_kernel<<<NCTA, NTHR, sizeof(Smem)>>>(
        x, Wih1, Whh1, bih1, bhh1, Wih2, Whh2, bih2, bhh2, Wlin, blin, out);
}

// round 9
// speedup vs baseline: 1.0718x; 1.0495x over previous
#include <cuda_runtime.h>
#include <cuda_bf16.h>

#define BATCH 1024
#define SEQ   512
#define HID   64
#define GATES 256
#define NR    8
#define NCTA  (BATCH / NR)   // 128
#define NTHR  384            // 12 warps: 8 L2-warps (4 k-groups x 2 halves) + 4 L1-warps

typedef unsigned long long ull;

struct __align__(16) Smem {
    // Weight layout: W[k][col], col = j*4 + hq (cell j, gate hq: 0=i,1=f,2=g,3=o)
    float W1[HID][GATES];          //  64 KB (W_hh1)
    float W2[2 * HID][GATES];      // 128 KB ([W_ih2 ; W_hh2])
    float hb[2 * HID][NR];         //   4 KB [k][row]; k<64: h1, k>=64: h2
    ulonglong2 pexA[4][3][64];     //  12 KB [pair][slot][cell] gates (i,f) — L2 only
    ulonglong2 pexB[4][3][64];     //  12 KB gates (g,o)
    float wih1v[GATES];
    float b1v[GATES];
    float b2v[GATES];
    float wlin[HID];
    float xs[2][NR];
    float outp[4][2][2];           // [pair][hh][row-in-pair]
    float blin;
};   // ~223.5 KB

__device__ __forceinline__ ull pk2(float lo, float hi) {
    ull r; asm("mov.b64 %0, {%1, %2};" : "=l"(r) : "f"(lo), "f"(hi)); return r;
}
__device__ __forceinline__ void unpk(ull v, float& lo, float& hi) {
    asm("mov.b64 {%0, %1}, %2;" : "=f"(lo), "=f"(hi) : "l"(v));
}
__device__ __forceinline__ void fma2(ull& d, ull a, ull b) {
    asm("fma.rn.f32x2 %0, %1, %2, %0;" : "+l"(d) : "l"(a), "l"(b));
}
__device__ __forceinline__ ull add2(ull a, ull b) {
    ull d; asm("add.rn.f32x2 %0, %1, %2;" : "=l"(d) : "l"(a), "l"(b)); return d;
}

// MUFU.TANH: single-instruction tanh (sm_75+), rel err ~2e-5
__device__ __forceinline__ float tanh_fast(float x) {
    float r; asm("tanh.approx.f32 %0, %1;" : "=f"(r) : "f"(x)); return r;
}
__device__ __forceinline__ float sigf(float v) {
    return fmaf(0.5f, tanh_fast(0.5f * v), 0.5f);
}
__device__ __forceinline__ float tanhf_(float v) {
    return tanh_fast(v);
}

// 8 k-steps: acc[q][p] += h[k][rows 2p,2p+1] * w[k][cell*4+q]
__device__ __forceinline__ void gemm8(const float* __restrict__ wp,
                                      const float* __restrict__ hp,
                                      ull acc[4][4]) {
#pragma unroll
    for (int kk = 0; kk < 8; kk++) {
        float4 wv = *reinterpret_cast<const float4*>(wp + kk * GATES);
        ulonglong2 hA = *reinterpret_cast<const ulonglong2*>(hp + kk * 8);
        ulonglong2 hB = *reinterpret_cast<const ulonglong2*>(hp + kk * 8 + 4);
        ull w;
        w = pk2(wv.x, wv.x);
        fma2(acc[0][0], hA.x, w); fma2(acc[0][1], hA.y, w);
        fma2(acc[0][2], hB.x, w); fma2(acc[0][3], hB.y, w);
        w = pk2(wv.y, wv.y);
        fma2(acc[1][0], hA.x, w); fma2(acc[1][1], hA.y, w);
        fma2(acc[1][2], hB.x, w); fma2(acc[1][3], hB.y, w);
        w = pk2(wv.z, wv.z);
        fma2(acc[2][0], hA.x, w); fma2(acc[2][1], hA.y, w);
        fma2(acc[2][2], hB.x, w); fma2(acc[2][3], hB.y, w);
        w = pk2(wv.w, wv.w);
        fma2(acc[3][0], hA.x, w); fma2(acc[3][1], hA.y, w);
        fma2(acc[3][2], hB.x, w); fma2(acc[3][3], hB.y, w);
    }
}

// LSTM cell for a packed row-pair: gates (i,f,g,o) each f32x2 -> h f32x2.
__device__ __forceinline__ ull act2(ull ai, ull af, ull ag, ull ao,
                                    float& ca, float& cb) {
    float i0, i1, f0, f1, g0, g1, o0, o1;
    unpk(ai, i0, i1); unpk(af, f0, f1);
    unpk(ag, g0, g1); unpk(ao, o0, o1);
    float cA = sigf(f0) * ca + sigf(i0) * tanhf_(g0);
    float cB = sigf(f1) * cb + sigf(i1) * tanhf_(g1);
    ca = cA; cb = cB;
    return pk2(sigf(o0) * tanhf_(cA), sigf(o1) * tanhf_(cB));
}

// Extract this group's row-pair with static indices (avoid local-mem demotion).
__device__ __forceinline__ void own_pair(const ull acc[4][4], int g,
                                         ull& ai, ull& af, ull& ag, ull& ao) {
    ai = 0; af = 0; ag = 0; ao = 0;
#pragma unroll
    for (int p = 0; p < 4; p++)
        if (p == g) { ai = acc[0][p]; af = acc[1][p]; ag = acc[2][p]; ao = acc[3][p]; }
}

__global__ void __launch_bounds__(NTHR, 1)
lstm_persistent_kernel(const float* __restrict__ x,
                       const float* __restrict__ Wih1, const float* __restrict__ Whh1,
                       const float* __restrict__ bih1, const float* __restrict__ bhh1,
                       const float* __restrict__ Wih2, const float* __restrict__ Whh2,
                       const float* __restrict__ bih2, const float* __restrict__ bhh2,
                       const float* __restrict__ Wlin, const float* __restrict__ blin,
                       float* __restrict__ out) {
    extern __shared__ char smem_raw[];
    Smem& sm = *reinterpret_cast<Smem*>(smem_raw);

    const int tid  = threadIdx.x;
    const int wid  = tid >> 5;
    const int lane = tid & 31;
    const int row0 = blockIdx.x * NR;

    // ---- one-time staging ----
    for (int i = tid; i < GATES * HID; i += NTHR) {
        int gsrc = i >> 6, k = i & 63;
        int col = (gsrc & 63) * 4 + (gsrc >> 6);
        sm.W1[k][col]      = Whh1[i];
        sm.W2[k][col]      = Wih2[i];
        sm.W2[64 + k][col] = Whh2[i];
    }
    for (int gsrc = tid; gsrc < GATES; gsrc += NTHR) {
        int col = (gsrc & 63) * 4 + (gsrc >> 6);
        sm.wih1v[col] = Wih1[gsrc];
        sm.b1v[col]   = bih1[gsrc] + bhh1[gsrc];
        sm.b2v[col]   = bih2[gsrc] + bhh2[gsrc];
    }
    if (tid < HID) sm.wlin[tid] = Wlin[tid];
    if (tid == 0)  sm.blin = blin[0];
    for (int i = tid; i < 2 * HID * NR; i += NTHR)
        reinterpret_cast<float*>(sm.hb)[i] = 0.0f;
    if (tid < NR) {
        sm.xs[1][tid] = x[(row0 + tid) * SEQ + 0];  // x(0) for prologue
        sm.xs[0][tid] = x[(row0 + tid) * SEQ + 1];  // x(1) for GEMM(0)
    }
    __syncthreads();

    const bool isL1 = (wid >= 8);
    const int g    = wid >> 1;                       // L2 group 0..3
    const int hh   = wid & 1;
    const int kh   = lane >> 4;                      // L1 k-half
    const int j    = isL1 ? ((wid - 8) * 16 + (lane & 15)) : (hh * 32 + lane);
    const int c4   = j * 4;

    // c-state: L2 threads hold c2 for pair g (2 cells); L1 threads hold c1 for
    // pairs (2kh, 2kh+1) (4 cells).
    float cs[4] = {0.f, 0.f, 0.f, 0.f};
    const float wl = sm.wlin[j];

    // ---- prologue: gates1(0) = b1 + x(0)*wih1  (h1(-1)=0), L1 warps ----
    if (isL1) {
        float4 wiv = *reinterpret_cast<const float4*>(&sm.wih1v[c4]);
        float4 bv  = *reinterpret_cast<const float4*>(&sm.b1v[c4]);
        ulonglong2 xq = *reinterpret_cast<const ulonglong2*>(&sm.xs[1][4 * kh]);
        ull gp0[4], gp1[4];
        float wivf[4] = {wiv.x, wiv.y, wiv.z, wiv.w};
        float bvf[4]  = {bv.x, bv.y, bv.z, bv.w};
#pragma unroll
        for (int q = 0; q < 4; q++) {
            ull b = pk2(bvf[q], bvf[q]);
            ull w = pk2(wivf[q], wivf[q]);
            gp0[q] = b; fma2(gp0[q], xq.x, w);
            gp1[q] = b; fma2(gp1[q], xq.y, w);
        }
        ull h0p = act2(gp0[0], gp0[1], gp0[2], gp0[3], cs[0], cs[1]);
        ull h1p = act2(gp1[0], gp1[1], gp1[2], gp1[3], cs[2], cs[3]);
        *reinterpret_cast<ulonglong2*>(&sm.hb[j][4 * kh]) = make_ulonglong2(h0p, h1p);
    }
    __syncthreads();

    for (int t = 0; t < SEQ; t++) {
        // finalize out[t-1]
        if (t > 0 && tid < NR) {
            out[(row0 + tid) * SEQ + (t - 1)] =
                sm.blin + sm.outp[tid >> 1][0][tid & 1] + sm.outp[tid >> 1][1][tid & 1];
        }

        // ===== GEMM phase (all 6 groups balanced at 512 FFMA2) =====
        ull acc[4][4];
        {
            // bias/x init
            if (!isL1 && g == 0) {
                float4 bv = *reinterpret_cast<const float4*>(&sm.b2v[c4]);
                ull b;
                b = pk2(bv.x, bv.x); acc[0][0]=b; acc[0][1]=b; acc[0][2]=b; acc[0][3]=b;
                b = pk2(bv.y, bv.y); acc[1][0]=b; acc[1][1]=b; acc[1][2]=b; acc[1][3]=b;
                b = pk2(bv.z, bv.z); acc[2][0]=b; acc[2][1]=b; acc[2][2]=b; acc[2][3]=b;
                b = pk2(bv.w, bv.w); acc[3][0]=b; acc[3][1]=b; acc[3][2]=b; acc[3][3]=b;
            } else if (isL1 && kh == 0) {
                float4 wiv = *reinterpret_cast<const float4*>(&sm.wih1v[c4]);
                float4 bv  = *reinterpret_cast<const float4*>(&sm.b1v[c4]);
                const float* xp = sm.xs[t & 1];   // x(t+1)
                ulonglong2 xA = *reinterpret_cast<const ulonglong2*>(xp);
                ulonglong2 xB = *reinterpret_cast<const ulonglong2*>(xp + 4);
                float wivf[4] = {wiv.x, wiv.y, wiv.z, wiv.w};
                float bvf[4]  = {bv.x, bv.y, bv.z, bv.w};
#pragma unroll
                for (int q = 0; q < 4; q++) {
                    ull b = pk2(bvf[q], bvf[q]);
                    ull w = pk2(wivf[q], wivf[q]);
                    acc[q][0] = b; fma2(acc[q][0], xA.x, w);
                    acc[q][1] = b; fma2(acc[q][1], xA.y, w);
                    acc[q][2] = b; fma2(acc[q][2], xB.x, w);
                    acc[q][3] = b; fma2(acc[q][3], xB.y, w);
                }
            } else {
#pragma unroll
                for (int q = 0; q < 4; q++)
#pragma unroll
                    for (int p = 0; p < 4; p++) acc[q][p] = 0ull;
            }
            // uniform 32-k GEMM (4 x gemm8)
            const float* wp;
            const float* hp;
            if (!isL1) {   // gates2(t): k in [g*32, g*32+32) of W2 over [h1;h2]
                wp = &sm.W2[g * 32][c4];
                hp = &sm.hb[g * 32][0];
            } else {       // gates1(t+1): k in [kh*32, kh*32+32) of W1 over h1(t)
                wp = &sm.W1[kh * 32][c4];
                hp = &sm.hb[kh * 32][0];
            }
#pragma unroll 1
            for (int kb = 0; kb < 4; kb++) {
                gemm8(wp, hp, acc);
                wp += 8 * GATES; hp += 8 * NR;
            }
        }

        // ship L2 partials (L1 exchanges via shuffle, no SMEM)
        if (!isL1) {
#pragma unroll
            for (int p = 0; p < 4; p++)
                if (p != g) {
                    int s = (g < p) ? g : g - 1;
                    sm.pexA[p][s][j] = make_ulonglong2(acc[0][p], acc[1][p]);
                    sm.pexB[p][s][j] = make_ulonglong2(acc[2][p], acc[3][p]);
                }
        }
        __syncthreads();

        // ===== ACT phase =====
        if (!isL1) {
            // reduce 4-way over SMEM, activate pair g -> h2(t)
            ull ai, af, ag, ao;
            own_pair(acc, g, ai, af, ag, ao);
#pragma unroll
            for (int s = 0; s < 3; s++) {
                ulonglong2 ra = sm.pexA[g][s][j];
                ulonglong2 rb = sm.pexB[g][s][j];
                ai = add2(ai, ra.x); af = add2(af, ra.y);
                ag = add2(ag, rb.x); ao = add2(ao, rb.y);
            }
            ull h2p = act2(ai, af, ag, ao, cs[0], cs[1]);
            *reinterpret_cast<ull*>(&sm.hb[64 + j][2 * g]) = h2p;

            // out(t) partials: rows 2g, 2g+1, reduced over this warp's 32 cells
            float h0, h1;
            unpk(h2p, h0, h1);
            float p0 = wl * h0, p1 = wl * h1;
#pragma unroll
            for (int off = 16; off > 0; off >>= 1) {
                p0 += __shfl_xor_sync(0xffffffffu, p0, off);
                p1 += __shfl_xor_sync(0xffffffffu, p1, off);
            }
            if (lane == 0) {
                sm.outp[g][hh][0] = p0;
                sm.outp[g][hh][1] = p1;
            }
        } else {
            // intra-warp 2-way k-reduce via xor-16 shuffle, activate pairs (2kh, 2kh+1)
            ull gp0[4], gp1[4];
#pragma unroll
            for (int q = 0; q < 4; q++) {
                ull s0 = kh ? acc[q][0] : acc[q][2];
                ull s1 = kh ? acc[q][1] : acc[q][3];
                ull r0 = __shfl_xor_sync(0xffffffffu, s0, 16);
                ull r1 = __shfl_xor_sync(0xffffffffu, s1, 16);
                ull o0 = kh ? acc[q][2] : acc[q][0];
                ull o1 = kh ? acc[q][3] : acc[q][1];
                gp0[q] = add2(o0, r0);
                gp1[q] = add2(o1, r1);
            }
            ull h0p = act2(gp0[0], gp0[1], gp0[2], gp0[3], cs[0], cs[1]);
            ull h1p = act2(gp1[0], gp1[1], gp1[2], gp1[3], cs[2], cs[3]);
            *reinterpret_cast<ulonglong2*>(&sm.hb[j][4 * kh]) = make_ulonglong2(h0p, h1p);
        }
        // prefetch x(t+2)
        if (tid < NR && (t + 2) < SEQ)
            sm.xs[(t + 1) & 1][tid] = x[(row0 + tid) * SEQ + t + 2];
        __syncthreads();
    }

    if (tid < NR) {
        out[(row0 + tid) * SEQ + (SEQ - 1)] =
            sm.blin + sm.outp[tid >> 1][0][tid & 1] + sm.outp[tid >> 1][1][tid & 1];
    }
}

extern "C" void kernel_launch(void* const* d_in, const int* in_sizes, int n_in,
                              void* d_out, int out_size) {
    const float* x     = (const float*)d_in[0];
    const float* Wih1  = (const float*)d_in[1];
    const float* Whh1  = (const float*)d_in[2];
    const float* bih1  = (const float*)d_in[3];
    const float* bhh1  = (const float*)d_in[4];
    const float* Wih2  = (const float*)d_in[5];
    const float* Whh2  = (const float*)d_in[6];
    const float* bih2  = (const float*)d_in[7];
    const float* bhh2  = (const float*)d_in[8];
    const float* Wlin  = (const float*)d_in[9];
    const float* blin  = (const float*)d_in[10];
    float* out = (float*)d_out;

    (void)in_sizes; (void)n_in; (void)out_size;

    static_assert(sizeof(Smem) <= 232448, "smem over sm_103a opt-in limit");
    cudaFuncSetAttribute(lstm_persistent_kernel,
                         cudaFuncAttributeMaxDynamicSharedMemorySize,
                         (int)sizeof(Smem));
    lstm_persistent_kernel<<<NCTA, NTHR, sizeof(Smem)>>>(
        x, Wih1, Whh1, bih1, bhh1, Wih2, Whh2, bih2, bhh2, Wlin, blin, out);
}